// round 11
// baseline (speedup 1.0000x reference)
#include <cuda_runtime.h>

// x: (32,3,16,32,32) fp32; weight: (3,16,3,3,3); bias scalar; out: (32,1,31,63,63)
// ConvTranspose3d s=2 p=1 k=3: per dim even o -> tap k=1 (i=o/2);
// odd o -> k=0 (i=(o+1)/2), k=2 (i=(o-1)/2). All in-range (od<=30, oh/ow<=62).

#define DIN 16
#define HIN 32
#define WIN 32
#define XCH (DIN*HIN*WIN)   // 16384
#define XB  (3*XCH)         // 49152
#define GSTR 20             // floats per (oc,kd,kh) group: 9 dup'd pairs + 2 pad = 80B
#define WSH (16*3*3*GSTR)   // 2880 floats
#define LOG2E 1.4426950408889634f

typedef unsigned long long ull;

__device__ __forceinline__ float ex2f(float x) {
    float r; asm("ex2.approx.ftz.f32 %0, %1;" : "=f"(r) : "f"(x)); return r;
}
__device__ __forceinline__ ull pk(float lo, float hi) {
    ull r; asm("mov.b64 %0, {%1, %2};" : "=l"(r) : "f"(lo), "f"(hi)); return r;
}
__device__ __forceinline__ float2 unpk(ull v) {
    float lo, hi; asm("mov.b64 {%0, %1}, %2;" : "=f"(lo), "=f"(hi) : "l"(v));
    return make_float2(lo, hi);
}
// d.lo += w.lo*x.lo; d.hi += w.hi*x.hi (two independent rn FMAs, bit-exact vs scalar)
__device__ __forceinline__ void ffma2(ull &d, ull w, ull x) {
    asm("fma.rn.f32x2 %0, %1, %2, %0;" : "+l"(d) : "l"(w), "l"(x));
}

// Weights: dup'd pairs, pre-scaled by log2(e) (accumulate in log2 domain; exp = EX2).
// sw[((oc*3+kd)*3+kh)*GSTR + 2*s + {0,1}], s = ic*3+kw.
__device__ __forceinline__ void load_weights(const float* __restrict__ w, float* sw) {
    for (int i = threadIdx.x; i < 1296; i += 128) {
        int ic = i / 432;  int r = i - ic * 432;
        int oc = r / 27;   int tap = r - oc * 27;
        int kd = tap / 9;  int t2 = tap - kd * 9;
        int kh = t2 / 3;   int kw = t2 - kh * 3;
        float v = w[i] * LOG2E;
        float* dst = sw + ((oc * 3 + kd) * 3 + kh) * GSTR + 2 * (ic * 3 + kw);
        dst[0] = v; dst[1] = v;
    }
}

__device__ __forceinline__ float finish(float s, float bv) {
    float l = __logf(s);   // s = sum e^conv
    float e = ex2f(fmaf(l, -LOG2E, -3.0f * LOG2E));   // e^{-(l+3)}
    float h = l * __frcp_rn((1.f + e) * 6.f);
    return fminf(fmaxf(h - bv, -1.f), 1.f);
}

// ---------------- width-8 FFMA2 path (classes with ND*NH <= 2) ----------------
// Lane c = lane&7: ow = 8c..8c+7 (c==7: ow 63 masked). 4 rows per warp.
// Pairs per (a,h,ic): P0=(x0,x1) P1=(x2,x3) from float4 (aligned, pack elides);
// S0=(x1,x2) S1=(x3,x4) hoisted shifted packs.
// Even outputs (VE0=(o0,o2), VE1=(o4,o6)): kw1 x P0/P1.
// Odd outputs (VO0=(o1,o3), VO1=(o5,o7)): kw0 x S0/S1, kw2 x P0/P1.
template<int ND, int NH>
__device__ __forceinline__ void run_oct(
    const float* __restrict__ xb, const float* __restrict__ sw,
    float* __restrict__ op, int id0, int id1, int ih0, int ih1, int c, float bv)
{
    ull P0[ND][NH][3], P1[ND][NH][3], S0[ND][NH][3], S1[ND][NH][3];
    int iw0 = 4 * c;
    int iw4 = (c < 7) ? iw0 + 4 : 31;   // clamp; only feeds masked ow=63
    #pragma unroll
    for (int a = 0; a < ND; a++) {
        int idv = (a == 0) ? id0 : id1;
        #pragma unroll
        for (int h = 0; h < NH; h++) {
            int ihv = (h == 0) ? ih0 : ih1;
            const float* p = xb + idv * (HIN * WIN) + ihv * WIN;
            #pragma unroll
            for (int ic = 0; ic < 3; ic++) {
                const float* q = p + ic * XCH;
                float4 t = __ldg((const float4*)(q + iw0));  // 16B aligned
                float x4 = __ldg(q + iw4);
                P0[a][h][ic] = pk(t.x, t.y);
                P1[a][h][ic] = pk(t.z, t.w);
                S0[a][h][ic] = pk(t.y, t.z);
                S1[a][h][ic] = pk(t.w, x4);
            }
        }
    }

    float s[8];
    #pragma unroll
    for (int k = 0; k < 8; k++) s[k] = 0.f;

    #pragma unroll
    for (int oc = 0; oc < 16; oc++) {
        ull VE0 = 0ull, VE1 = 0ull, VO0 = 0ull, VO1 = 0ull;   // 0 bits == (0.f,0.f)
        #pragma unroll
        for (int a = 0; a < ND; a++) {
            const int KD = (ND == 1) ? 1 : a * 2;
            #pragma unroll
            for (int h = 0; h < NH; h++) {
                const int KH = (NH == 1) ? 1 : h * 2;
                const float* gf = sw + ((oc * 3 + KD) * 3 + KH) * GSTR;
                ulonglong2 W01 = ((const ulonglong2*)gf)[0];  // dup pairs s0,s1
                ulonglong2 W23 = ((const ulonglong2*)gf)[1];  // s2,s3
                ulonglong2 W45 = ((const ulonglong2*)gf)[2];  // s4,s5
                ulonglong2 W67 = ((const ulonglong2*)gf)[3];  // s6,s7
                ull        W8  = ((const ull*)gf)[8];         // s8
                // even: kw1 slots 1,4,7
                ffma2(VE0, W01.y, P0[a][h][0]); ffma2(VE1, W01.y, P1[a][h][0]);
                ffma2(VE0, W45.x, P0[a][h][1]); ffma2(VE1, W45.x, P1[a][h][1]);
                ffma2(VE0, W67.y, P0[a][h][2]); ffma2(VE1, W67.y, P1[a][h][2]);
                // odd kw0: slots 0,3,6 x shifted pairs
                ffma2(VO0, W01.x, S0[a][h][0]); ffma2(VO1, W01.x, S1[a][h][0]);
                ffma2(VO0, W23.y, S0[a][h][1]); ffma2(VO1, W23.y, S1[a][h][1]);
                ffma2(VO0, W67.x, S0[a][h][2]); ffma2(VO1, W67.x, S1[a][h][2]);
                // odd kw2: slots 2,5,8 x aligned pairs
                ffma2(VO0, W23.x, P0[a][h][0]); ffma2(VO1, W23.x, P1[a][h][0]);
                ffma2(VO0, W45.y, P0[a][h][1]); ffma2(VO1, W45.y, P1[a][h][1]);
                ffma2(VO0, W8,    P0[a][h][2]); ffma2(VO1, W8,    P1[a][h][2]);
            }
        }
        float2 e0 = unpk(VE0), e1 = unpk(VE1), o0 = unpk(VO0), o1 = unpk(VO1);
        s[0] += ex2f(e0.x); s[2] += ex2f(e0.y);
        s[4] += ex2f(e1.x); s[6] += ex2f(e1.y);
        s[1] += ex2f(o0.x); s[3] += ex2f(o0.y);
        s[5] += ex2f(o1.x); s[7] += ex2f(o1.y);
    }

    int wb = 8 * c;
    #pragma unroll
    for (int k = 0; k < 7; k++) op[wb + k] = finish(s[k], bv);
    if (c < 7) op[wb + 7] = finish(s[7], bv);
}

// ---------------- width-4 FFMA2 path (class 3: odd od, odd oh) ----------------
// Lane c = lane&15: ow = 4c..4c+3. P=(x0,x1) from float2 (aligned), S=(x1,x2).
__device__ __forceinline__ void run_quad22(
    const float* __restrict__ xb, const float* __restrict__ sw,
    float* __restrict__ op, int id0, int id1, int ih0, int ih1, int c, float bv)
{
    ull P[2][2][3], S[2][2][3];
    int iw0 = 2 * c;
    int iw2 = (c < 15) ? iw0 + 2 : 31;   // clamp; only feeds masked ow=63
    #pragma unroll
    for (int a = 0; a < 2; a++) {
        int idv = (a == 0) ? id0 : id1;
        #pragma unroll
        for (int h = 0; h < 2; h++) {
            int ihv = (h == 0) ? ih0 : ih1;
            const float* p = xb + idv * (HIN * WIN) + ihv * WIN;
            #pragma unroll
            for (int ic = 0; ic < 3; ic++) {
                const float* q = p + ic * XCH;
                float2 t = __ldg((const float2*)(q + iw0));
                float x2 = __ldg(q + iw2);
                P[a][h][ic] = pk(t.x, t.y);
                S[a][h][ic] = pk(t.y, x2);
            }
        }
    }

    float s0 = 0.f, s1 = 0.f, s2 = 0.f, s3 = 0.f;
    #pragma unroll
    for (int oc = 0; oc < 16; oc++) {
        ull VE = 0ull, VO = 0ull;   // (v0,v2) and (v1,v3)
        #pragma unroll
        for (int a = 0; a < 2; a++) {
            const int KD = a * 2;
            #pragma unroll
            for (int h = 0; h < 2; h++) {
                const int KH = h * 2;
                const float* gf = sw + ((oc * 3 + KD) * 3 + KH) * GSTR;
                ulonglong2 W01 = ((const ulonglong2*)gf)[0];
                ulonglong2 W23 = ((const ulonglong2*)gf)[1];
                ulonglong2 W45 = ((const ulonglong2*)gf)[2];
                ulonglong2 W67 = ((const ulonglong2*)gf)[3];
                ull        W8  = ((const ull*)gf)[8];
                // even: kw1 slots 1,4,7
                ffma2(VE, W01.y, P[a][h][0]);
                ffma2(VE, W45.x, P[a][h][1]);
                ffma2(VE, W67.y, P[a][h][2]);
                // odd kw0: slots 0,3,6 x S
                ffma2(VO, W01.x, S[a][h][0]);
                ffma2(VO, W23.y, S[a][h][1]);
                ffma2(VO, W67.x, S[a][h][2]);
                // odd kw2: slots 2,5,8 x P
                ffma2(VO, W23.x, P[a][h][0]);
                ffma2(VO, W45.y, P[a][h][1]);
                ffma2(VO, W8,    P[a][h][2]);
            }
        }
        float2 e = unpk(VE), o = unpk(VO);
        s0 += ex2f(e.x); s2 += ex2f(e.y);
        s1 += ex2f(o.x); s3 += ex2f(o.y);
    }

    int wb = 4 * c;
    op[wb]     = finish(s0, bv);
    op[wb + 1] = finish(s1, bv);
    op[wb + 2] = finish(s2, bv);
    if (wb + 3 < 63) op[wb + 3] = finish(s3, bv);
}

// Merged kernel, 128-thread blocks, >=7 blocks/SM (caps regs at 73).
// Block ranges (cls3 first = heaviest blocks start in wave 0):
//   [0,1860):     cls3, width-4,  8 rows/block (14880 rows)
//   [1860,2884):  cls0, width-8, 16 rows/block (16384 rows)
//   [2884,3876):  cls1, width-8 (15872 rows)
//   [3876,4836):  cls2, width-8 (15360 rows)
__global__ __launch_bounds__(128, 7)
void convT_lse_v11(const float* __restrict__ x, const float* __restrict__ w,
                   const float* __restrict__ bias, float* __restrict__ out)
{
    __shared__ __align__(16) float sw[WSH];
    load_weights(w, sw);
    __syncthreads();

    int warp = threadIdx.x >> 5, lane = threadIdx.x & 31;
    float bv = __ldg(bias);
    int blk = blockIdx.x;

    if (blk < 1860) {
        int half = lane >> 4, c = lane & 15;
        int r = (blk * 4 + warp) * 2 + half;
        const int per_b = 15 * 31;
        int b = r / per_b; int rem = r - b * per_b;
        int idd = rem / 31; int ihh = rem - idd * 31;
        int od = 2 * idd + 1, oh = 2 * ihh + 1;
        const float* xb = x + (size_t)b * XB;
        float* op = out + ((size_t)(b * 31 + od) * 63 + oh) * 63;
        int id0 = (od + 1) >> 1, id1 = (od - 1) >> 1;
        int ih0 = (oh + 1) >> 1, ih1 = (oh - 1) >> 1;
        run_quad22(xb, sw, op, id0, id1, ih0, ih1, c, bv);
        return;
    }

    int rloc = lane >> 3, c = lane & 7;
    int cls, rb;
    if (blk < 2884)      { cls = 0; rb = (blk - 1860) * 16; }
    else if (blk < 3876) { cls = 1; rb = (blk - 2884) * 16; }
    else                 { cls = 2; rb = (blk - 3876) * 16; }
    int r = rb + warp * 4 + rloc;

    int pd = (cls == 2), ph = (cls == 1);
    int nhc = ph ? 31 : 32;
    int per_b = (pd ? 15 : 16) * nhc;
    int b = r / per_b; int rem = r - b * per_b;
    int idd = rem / nhc; int ihh = rem - idd * nhc;
    int od = 2 * idd + pd, oh = 2 * ihh + ph;

    const float* xb = x + (size_t)b * XB;
    float* op = out + ((size_t)(b * 31 + od) * 63 + oh) * 63;

    int id0, id1 = 0, ih0, ih1 = 0;
    if (pd) { id0 = (od + 1) >> 1; id1 = (od - 1) >> 1; } else id0 = od >> 1;
    if (ph) { ih0 = (oh + 1) >> 1; ih1 = (oh - 1) >> 1; } else ih0 = oh >> 1;

    if (cls == 0)      run_oct<1, 1>(xb, sw, op, id0, id1, ih0, ih1, c, bv);
    else if (cls == 1) run_oct<1, 2>(xb, sw, op, id0, id1, ih0, ih1, c, bv);
    else               run_oct<2, 1>(xb, sw, op, id0, id1, ih0, ih1, c, bv);
}

extern "C" void kernel_launch(void* const* d_in, const int* in_sizes, int n_in,
                              void* d_out, int out_size)
{
    const float* x    = (const float*)d_in[0];
    const float* w    = (const float*)d_in[1];
    const float* bias = (const float*)d_in[2];
    float* out        = (float*)d_out;

    convT_lse_v11<<<4836, 128>>>(x, w, bias, out);
}

// round 12
// speedup vs baseline: 1.0718x; 1.0718x over previous
#include <cuda_runtime.h>

// x: (32,3,16,32,32) fp32; weight: (3,16,3,3,3); bias scalar; out: (32,1,31,63,63)
// ConvTranspose3d s=2 p=1 k=3: per dim even o -> tap k=1 (i=o/2);
// odd o -> k=0 (i=(o+1)/2), k=2 (i=(o-1)/2). All in-range (od<=30, oh/ow<=62).

#define DIN 16
#define HIN 32
#define WIN 32
#define XCH (DIN*HIN*WIN)   // 16384
#define XB  (3*XCH)         // 49152
#define WSH (16*3*3*12)     // sw[oc][kd][kh][slot], slot=ic*3+kw (9 used, pad 12)
#define LOG2E 1.4426950408889634f

__device__ __forceinline__ float ex2f(float x) {
    float r; asm("ex2.approx.ftz.f32 %0, %1;" : "=f"(r) : "f"(x)); return r;
}

// Weights pre-scaled by log2(e): conv accumulators live in log2 domain; exp = one EX2.
__device__ __forceinline__ void load_weights(const float* __restrict__ w, float* sw) {
    // src w[ic*432 + oc*27 + kd*9 + kh*3 + kw]
    for (int i = threadIdx.x; i < 1296; i += 128) {
        int ic = i / 432;  int r = i - ic * 432;
        int oc = r / 27;   int tap = r - oc * 27;
        int kd = tap / 9;  int t2 = tap - kd * 9;
        int kh = t2 / 3;   int kw = t2 - kh * 3;
        sw[((oc * 3 + kd) * 3 + kh) * 12 + ic * 3 + kw] = w[i] * LOG2E;
    }
}

__device__ __forceinline__ float finish(float s, float bv) {
    float l = __logf(s);   // s = sum e^conv
    // fast sigmoid: MUFU.EX2 + MUFU.RCP paths only
    float e = ex2f(fmaf(l, -LOG2E, -3.0f * LOG2E));   // e^{-(l+3)}
    float h = __fdividef(l, (1.f + e) * 6.f);
    return fminf(fmaxf(h - bv, -1.f), 1.f);
}

// ---------------- width-8 path (classes with ND*NH <= 2) ----------------
// Lane c = lane&7 handles ow = 8c..8c+7 (c==7: ow 63 masked). 4 rows per warp.
template<int ND, int NH>
__device__ __forceinline__ void run_oct(
    const float* __restrict__ xb, const float* __restrict__ sw,
    float* __restrict__ op, int id0, int id1, int ih0, int ih1, int c, float bv)
{
    float xv[ND][NH][3][5];
    int iw0 = 4 * c;
    int iw4 = (c < 7) ? iw0 + 4 : 31;   // clamp; only feeds masked ow=63
    #pragma unroll
    for (int a = 0; a < ND; a++) {
        int idv = (a == 0) ? id0 : id1;
        #pragma unroll
        for (int h = 0; h < NH; h++) {
            int ihv = (h == 0) ? ih0 : ih1;
            const float* p = xb + idv * (HIN * WIN) + ihv * WIN;
            #pragma unroll
            for (int ic = 0; ic < 3; ic++) {
                const float* q = p + ic * XCH;
                float4 t = __ldg((const float4*)(q + iw0));  // 16B aligned
                xv[a][h][ic][0] = t.x; xv[a][h][ic][1] = t.y;
                xv[a][h][ic][2] = t.z; xv[a][h][ic][3] = t.w;
                xv[a][h][ic][4] = __ldg(q + iw4);
            }
        }
    }

    float s[8];
    #pragma unroll
    for (int k = 0; k < 8; k++) s[k] = 0.f;

    // Partial unroll: keeps the body inside L0 I$ (full 16x unroll = ~14KB/class,
    // 4 classes thrash the ~6KB L0); address math folds to one uniform increment.
    #pragma unroll 4
    for (int oc = 0; oc < 16; oc++) {
        float v[8];
        #pragma unroll
        for (int k = 0; k < 8; k++) v[k] = 0.f;
        #pragma unroll
        for (int a = 0; a < ND; a++) {
            const int KD = (ND == 1) ? 1 : a * 2;
            #pragma unroll
            for (int h = 0; h < NH; h++) {
                const int KH = (NH == 1) ? 1 : h * 2;
                const float* g = sw + ((oc * 3 + KD) * 3 + KH) * 12;
                float4 A = *(const float4*)g;
                float4 B = *(const float4*)(g + 4);
                float  C = g[8];
                #pragma unroll
                for (int t = 0; t < 4; t++) {
                    float x0t = xv[a][h][0][t], x1t = xv[a][h][1][t], x2t = xv[a][h][2][t];
                    float x0n = xv[a][h][0][t+1], x1n = xv[a][h][1][t+1], x2n = xv[a][h][2][t+1];
                    v[2*t]   = fmaf(A.y, x0t, v[2*t]);
                    v[2*t]   = fmaf(B.x, x1t, v[2*t]);
                    v[2*t]   = fmaf(B.w, x2t, v[2*t]);
                    v[2*t+1] = fmaf(A.x, x0n, v[2*t+1]);
                    v[2*t+1] = fmaf(A.w, x1n, v[2*t+1]);
                    v[2*t+1] = fmaf(B.z, x2n, v[2*t+1]);
                    v[2*t+1] = fmaf(A.z, x0t, v[2*t+1]);
                    v[2*t+1] = fmaf(B.y, x1t, v[2*t+1]);
                    v[2*t+1] = fmaf(C,   x2t, v[2*t+1]);
                }
            }
        }
        #pragma unroll
        for (int k = 0; k < 8; k++) s[k] += ex2f(v[k]);   // v in log2 domain
    }

    int wb = 8 * c;
    #pragma unroll
    for (int k = 0; k < 7; k++) op[wb + k] = finish(s[k], bv);
    if (c < 7) op[wb + 7] = finish(s[7], bv);
}

// ---------------- width-4 path (class 3: odd od, odd oh) ----------------
__device__ __forceinline__ void run_quad22(
    const float* __restrict__ xb, const float* __restrict__ sw,
    float* __restrict__ op, int id0, int id1, int ih0, int ih1, int c, float bv)
{
    float xv[2][2][3][3];
    int iw0 = 2 * c;
    int iw2 = (c < 15) ? iw0 + 2 : 31;
    #pragma unroll
    for (int a = 0; a < 2; a++) {
        int idv = (a == 0) ? id0 : id1;
        #pragma unroll
        for (int h = 0; h < 2; h++) {
            int ihv = (h == 0) ? ih0 : ih1;
            const float* p = xb + idv * (HIN * WIN) + ihv * WIN;
            #pragma unroll
            for (int ic = 0; ic < 3; ic++) {
                const float* q = p + ic * XCH;
                float2 t = __ldg((const float2*)(q + iw0));
                xv[a][h][ic][0] = t.x;
                xv[a][h][ic][1] = t.y;
                xv[a][h][ic][2] = __ldg(q + iw2);
            }
        }
    }

    float s0 = 0.f, s1 = 0.f, s2 = 0.f, s3 = 0.f;
    #pragma unroll 4
    for (int oc = 0; oc < 16; oc++) {
        float v0 = 0.f, v1 = 0.f, v2 = 0.f, v3 = 0.f;
        #pragma unroll
        for (int a = 0; a < 2; a++) {
            const int KD = a * 2;
            #pragma unroll
            for (int h = 0; h < 2; h++) {
                const int KH = h * 2;
                const float* g = sw + ((oc * 3 + KD) * 3 + KH) * 12;
                float4 A = *(const float4*)g;
                float4 B = *(const float4*)(g + 4);
                float  C = g[8];
                float x00 = xv[a][h][0][0], x01 = xv[a][h][0][1], x02 = xv[a][h][0][2];
                float x10 = xv[a][h][1][0], x11 = xv[a][h][1][1], x12 = xv[a][h][1][2];
                float x20 = xv[a][h][2][0], x21 = xv[a][h][2][1], x22 = xv[a][h][2][2];
                v0 = fmaf(A.y, x00, v0); v0 = fmaf(B.x, x10, v0); v0 = fmaf(B.w, x20, v0);
                v2 = fmaf(A.y, x01, v2); v2 = fmaf(B.x, x11, v2); v2 = fmaf(B.w, x21, v2);
                v1 = fmaf(A.x, x01, v1); v1 = fmaf(A.w, x11, v1); v1 = fmaf(B.z, x21, v1);
                v1 = fmaf(A.z, x00, v1); v1 = fmaf(B.y, x10, v1); v1 = fmaf(C,   x20, v1);
                v3 = fmaf(A.x, x02, v3); v3 = fmaf(A.w, x12, v3); v3 = fmaf(B.z, x22, v3);
                v3 = fmaf(A.z, x01, v3); v3 = fmaf(B.y, x11, v3); v3 = fmaf(C,   x21, v3);
            }
        }
        s0 += ex2f(v0); s1 += ex2f(v1); s2 += ex2f(v2); s3 += ex2f(v3);
    }

    int wb = 4 * c;
    op[wb]     = finish(s0, bv);
    op[wb + 1] = finish(s1, bv);
    op[wb + 2] = finish(s2, bv);
    if (wb + 3 < 63) op[wb + 3] = finish(s3, bv);
}

// Merged kernel, 128-thread blocks, min 8 blocks/SM (forces regs <= 64).
// Block ranges (cls3 first = heaviest blocks start in wave 0):
//   [0,1860):     cls3, width-4,  8 rows/block (14880 rows)
//   [1860,2884):  cls0, width-8, 16 rows/block (16384 rows)
//   [2884,3876):  cls1, width-8 (15872 rows)
//   [3876,4836):  cls2, width-8 (15360 rows)
__global__ __launch_bounds__(128, 8)
void convT_lse_v12(const float* __restrict__ x, const float* __restrict__ w,
                   const float* __restrict__ bias, float* __restrict__ out)
{
    __shared__ __align__(16) float sw[WSH];
    load_weights(w, sw);
    __syncthreads();

    int warp = threadIdx.x >> 5, lane = threadIdx.x & 31;
    float bv = __ldg(bias);
    int blk = blockIdx.x;

    if (blk < 1860) {
        // class 3 (odd od, odd oh), width 4, 8 rows/block
        int half = lane >> 4, c = lane & 15;
        int r = (blk * 4 + warp) * 2 + half;
        const int per_b = 15 * 31;
        int b = r / per_b; int rem = r - b * per_b;
        int idd = rem / 31; int ihh = rem - idd * 31;
        int od = 2 * idd + 1, oh = 2 * ihh + 1;
        const float* xb = x + (size_t)b * XB;
        float* op = out + ((size_t)(b * 31 + od) * 63 + oh) * 63;
        int id0 = (od + 1) >> 1, id1 = (od - 1) >> 1;
        int ih0 = (oh + 1) >> 1, ih1 = (oh - 1) >> 1;
        run_quad22(xb, sw, op, id0, id1, ih0, ih1, c, bv);
        return;
    }

    // width-8 classes, 16 rows/block
    int rloc = lane >> 3, c = lane & 7;
    int cls, rb;
    if (blk < 2884)      { cls = 0; rb = (blk - 1860) * 16; }
    else if (blk < 3876) { cls = 1; rb = (blk - 2884) * 16; }
    else                 { cls = 2; rb = (blk - 3876) * 16; }
    int r = rb + warp * 4 + rloc;

    int pd = (cls == 2), ph = (cls == 1);
    int nhc = ph ? 31 : 32;
    int per_b = (pd ? 15 : 16) * nhc;
    int b = r / per_b; int rem = r - b * per_b;
    int idd = rem / nhc; int ihh = rem - idd * nhc;
    int od = 2 * idd + pd, oh = 2 * ihh + ph;

    const float* xb = x + (size_t)b * XB;
    float* op = out + ((size_t)(b * 31 + od) * 63 + oh) * 63;

    int id0, id1 = 0, ih0, ih1 = 0;
    if (pd) { id0 = (od + 1) >> 1; id1 = (od - 1) >> 1; } else id0 = od >> 1;
    if (ph) { ih0 = (oh + 1) >> 1; ih1 = (oh - 1) >> 1; } else ih0 = oh >> 1;

    if (cls == 0)      run_oct<1, 1>(xb, sw, op, id0, id1, ih0, ih1, c, bv);
    else if (cls == 1) run_oct<1, 2>(xb, sw, op, id0, id1, ih0, ih1, c, bv);
    else               run_oct<2, 1>(xb, sw, op, id0, id1, ih0, ih1, c, bv);
}

extern "C" void kernel_launch(void* const* d_in, const int* in_sizes, int n_in,
                              void* d_out, int out_size)
{
    const float* x    = (const float*)d_in[0];
    const float* w    = (const float*)d_in[1];
    const float* bias = (const float*)d_in[2];
    float* out        = (float*)d_out;

    convT_lse_v12<<<4836, 128>>>(x, w, bias, out);
}

// round 13
// speedup vs baseline: 1.2003x; 1.1199x over previous
#include <cuda_runtime.h>

// x: (32,3,16,32,32) fp32; weight: (3,16,3,3,3); bias scalar; out: (32,1,31,63,63)
// ConvTranspose3d s=2 p=1 k=3: per dim even o -> tap k=1 (i=o/2);
// odd o -> k=0 (i=(o+1)/2), k=2 (i=(o-1)/2). All in-range (od<=30, oh/ow<=62).

#define DIN 16
#define HIN 32
#define WIN 32
#define XCH (DIN*HIN*WIN)   // 16384
#define XB  (3*XCH)         // 49152
#define WSH (16*3*3*12)     // sw[oc][kd][kh][slot], slot=ic*3+kw (9 used, pad 12)
#define LOG2E 1.4426950408889634f
#define LN2   0.6931471805599453f

__device__ __forceinline__ float ex2f(float x) {
    float r; asm("ex2.approx.ftz.f32 %0, %1;" : "=f"(r) : "f"(x)); return r;
}
__device__ __forceinline__ float lg2f(float x) {
    float r; asm("lg2.approx.ftz.f32 %0, %1;" : "=f"(r) : "f"(x)); return r;
}

// Weights pre-scaled by log2(e): conv accumulators live in log2 domain; exp = one EX2.
__device__ __forceinline__ void load_weights(const float* __restrict__ w, float* sw) {
    // src w[ic*432 + oc*27 + kd*9 + kh*3 + kw]
    for (int i = threadIdx.x; i < 1296; i += 128) {
        int ic = i / 432;  int r = i - ic * 432;
        int oc = r / 27;   int tap = r - oc * 27;
        int kd = tap / 9;  int t2 = tap - kd * 9;
        int kh = t2 / 3;   int kw = t2 - kh * 3;
        sw[((oc * 3 + kd) * 3 + kh) * 12 + ic * 3 + kw] = w[i] * LOG2E;
    }
}

// s = sum_oc e^conv. Pure MUFU epilogue (LG2/EX2/RCP), no Newton FFMAs:
//   l2 = log2(s); l = l2*ln2; e^{-(l+3)} = 2^{-l2 - 3*log2e};
//   h = l / (6 + 6e); out = clip(h - bias, -1, 1)
__device__ __forceinline__ float finish(float s, float bv) {
    float l2 = lg2f(s);
    float e  = ex2f(-l2 - 3.0f * LOG2E);
    float l  = l2 * LN2;
    float h  = __fdividef(l, fmaf(e, 6.f, 6.f));
    return fminf(fmaxf(h - bv, -1.f), 1.f);
}

// ---------------- width-8 path (classes with ND*NH <= 2) ----------------
// Lane c = lane&7 handles ow = 8c..8c+7 (c==7: ow 63 masked). 4 rows per warp.
template<int ND, int NH>
__device__ __forceinline__ void run_oct(
    const float* __restrict__ xb, const float* __restrict__ sw,
    float* __restrict__ op, int id0, int id1, int ih0, int ih1, int c, float bv)
{
    float xv[ND][NH][3][5];
    int iw0 = 4 * c;
    int iw4 = (c < 7) ? iw0 + 4 : 31;   // clamp; only feeds masked ow=63
    #pragma unroll
    for (int a = 0; a < ND; a++) {
        int idv = (a == 0) ? id0 : id1;
        #pragma unroll
        for (int h = 0; h < NH; h++) {
            int ihv = (h == 0) ? ih0 : ih1;
            const float* p = xb + idv * (HIN * WIN) + ihv * WIN;
            #pragma unroll
            for (int ic = 0; ic < 3; ic++) {
                const float* q = p + ic * XCH;
                float4 t = __ldg((const float4*)(q + iw0));  // 16B aligned
                xv[a][h][ic][0] = t.x; xv[a][h][ic][1] = t.y;
                xv[a][h][ic][2] = t.z; xv[a][h][ic][3] = t.w;
                xv[a][h][ic][4] = __ldg(q + iw4);
            }
        }
    }

    float s[8];
    #pragma unroll
    for (int k = 0; k < 8; k++) s[k] = 0.f;

    #pragma unroll
    for (int oc = 0; oc < 16; oc++) {     // full unroll (v10-proven)
        float v[8];
        #pragma unroll
        for (int k = 0; k < 8; k++) v[k] = 0.f;
        #pragma unroll
        for (int a = 0; a < ND; a++) {
            const int KD = (ND == 1) ? 1 : a * 2;
            #pragma unroll
            for (int h = 0; h < NH; h++) {
                const int KH = (NH == 1) ? 1 : h * 2;
                const float* g = sw + ((oc * 3 + KD) * 3 + KH) * 12;
                float4 A = *(const float4*)g;
                float4 B = *(const float4*)(g + 4);
                float  C = g[8];
                #pragma unroll
                for (int t = 0; t < 4; t++) {
                    float x0t = xv[a][h][0][t], x1t = xv[a][h][1][t], x2t = xv[a][h][2][t];
                    float x0n = xv[a][h][0][t+1], x1n = xv[a][h][1][t+1], x2n = xv[a][h][2][t+1];
                    v[2*t]   = fmaf(A.y, x0t, v[2*t]);
                    v[2*t]   = fmaf(B.x, x1t, v[2*t]);
                    v[2*t]   = fmaf(B.w, x2t, v[2*t]);
                    v[2*t+1] = fmaf(A.x, x0n, v[2*t+1]);
                    v[2*t+1] = fmaf(A.w, x1n, v[2*t+1]);
                    v[2*t+1] = fmaf(B.z, x2n, v[2*t+1]);
                    v[2*t+1] = fmaf(A.z, x0t, v[2*t+1]);
                    v[2*t+1] = fmaf(B.y, x1t, v[2*t+1]);
                    v[2*t+1] = fmaf(C,   x2t, v[2*t+1]);
                }
            }
        }
        #pragma unroll
        for (int k = 0; k < 8; k++) s[k] += ex2f(v[k]);   // v in log2 domain
    }

    int wb = 8 * c;
    #pragma unroll
    for (int k = 0; k < 7; k++) op[wb + k] = finish(s[k], bv);
    if (c < 7) op[wb + 7] = finish(s[7], bv);
}

// ---------------- width-4 path (class 3: odd od, odd oh) ----------------
__device__ __forceinline__ void run_quad22(
    const float* __restrict__ xb, const float* __restrict__ sw,
    float* __restrict__ op, int id0, int id1, int ih0, int ih1, int c, float bv)
{
    float xv[2][2][3][3];
    int iw0 = 2 * c;
    int iw2 = (c < 15) ? iw0 + 2 : 31;
    #pragma unroll
    for (int a = 0; a < 2; a++) {
        int idv = (a == 0) ? id0 : id1;
        #pragma unroll
        for (int h = 0; h < 2; h++) {
            int ihv = (h == 0) ? ih0 : ih1;
            const float* p = xb + idv * (HIN * WIN) + ihv * WIN;
            #pragma unroll
            for (int ic = 0; ic < 3; ic++) {
                const float* q = p + ic * XCH;
                float2 t = __ldg((const float2*)(q + iw0));
                xv[a][h][ic][0] = t.x;
                xv[a][h][ic][1] = t.y;
                xv[a][h][ic][2] = __ldg(q + iw2);
            }
        }
    }

    float s0 = 0.f, s1 = 0.f, s2 = 0.f, s3 = 0.f;
    #pragma unroll
    for (int oc = 0; oc < 16; oc++) {
        float v0 = 0.f, v1 = 0.f, v2 = 0.f, v3 = 0.f;
        #pragma unroll
        for (int a = 0; a < 2; a++) {
            const int KD = a * 2;
            #pragma unroll
            for (int h = 0; h < 2; h++) {
                const int KH = h * 2;
                const float* g = sw + ((oc * 3 + KD) * 3 + KH) * 12;
                float4 A = *(const float4*)g;
                float4 B = *(const float4*)(g + 4);
                float  C = g[8];
                float x00 = xv[a][h][0][0], x01 = xv[a][h][0][1], x02 = xv[a][h][0][2];
                float x10 = xv[a][h][1][0], x11 = xv[a][h][1][1], x12 = xv[a][h][1][2];
                float x20 = xv[a][h][2][0], x21 = xv[a][h][2][1], x22 = xv[a][h][2][2];
                v0 = fmaf(A.y, x00, v0); v0 = fmaf(B.x, x10, v0); v0 = fmaf(B.w, x20, v0);
                v2 = fmaf(A.y, x01, v2); v2 = fmaf(B.x, x11, v2); v2 = fmaf(B.w, x21, v2);
                v1 = fmaf(A.x, x01, v1); v1 = fmaf(A.w, x11, v1); v1 = fmaf(B.z, x21, v1);
                v1 = fmaf(A.z, x00, v1); v1 = fmaf(B.y, x10, v1); v1 = fmaf(C,   x20, v1);
                v3 = fmaf(A.x, x02, v3); v3 = fmaf(A.w, x12, v3); v3 = fmaf(B.z, x22, v3);
                v3 = fmaf(A.z, x01, v3); v3 = fmaf(B.y, x11, v3); v3 = fmaf(C,   x21, v3);
            }
        }
        s0 += ex2f(v0); s1 += ex2f(v1); s2 += ex2f(v2); s3 += ex2f(v3);
    }

    int wb = 4 * c;
    op[wb]     = finish(s0, bv);
    op[wb + 1] = finish(s1, bv);
    op[wb + 2] = finish(s2, bv);
    if (wb + 3 < 63) op[wb + 3] = finish(s3, bv);
}

// Merged kernel, 128-thread blocks, min 8 blocks/SM (forces regs <= 64).
// Block ranges (cls3 first = heaviest blocks start in wave 0):
//   [0,1860):     cls3, width-4,  8 rows/block (14880 rows)
//   [1860,2884):  cls0, width-8, 16 rows/block (16384 rows)
//   [2884,3876):  cls1, width-8 (15872 rows)
//   [3876,4836):  cls2, width-8 (15360 rows)
__global__ __launch_bounds__(128, 8)
void convT_lse_v13(const float* __restrict__ x, const float* __restrict__ w,
                   const float* __restrict__ bias, float* __restrict__ out)
{
    __shared__ __align__(16) float sw[WSH];
    load_weights(w, sw);
    __syncthreads();

    int warp = threadIdx.x >> 5, lane = threadIdx.x & 31;
    float bv = __ldg(bias);
    int blk = blockIdx.x;

    if (blk < 1860) {
        // class 3 (odd od, odd oh), width 4, 8 rows/block
        int half = lane >> 4, c = lane & 15;
        int r = (blk * 4 + warp) * 2 + half;
        const int per_b = 15 * 31;
        int b = r / per_b; int rem = r - b * per_b;
        int idd = rem / 31; int ihh = rem - idd * 31;
        int od = 2 * idd + 1, oh = 2 * ihh + 1;
        const float* xb = x + (size_t)b * XB;
        float* op = out + ((size_t)(b * 31 + od) * 63 + oh) * 63;
        int id0 = (od + 1) >> 1, id1 = (od - 1) >> 1;
        int ih0 = (oh + 1) >> 1, ih1 = (oh - 1) >> 1;
        run_quad22(xb, sw, op, id0, id1, ih0, ih1, c, bv);
        return;
    }

    // width-8 classes, 16 rows/block
    int rloc = lane >> 3, c = lane & 7;
    int cls, rb;
    if (blk < 2884)      { cls = 0; rb = (blk - 1860) * 16; }
    else if (blk < 3876) { cls = 1; rb = (blk - 2884) * 16; }
    else                 { cls = 2; rb = (blk - 3876) * 16; }
    int r = rb + warp * 4 + rloc;

    int pd = (cls == 2), ph = (cls == 1);
    int nhc = ph ? 31 : 32;
    int per_b = (pd ? 15 : 16) * nhc;
    int b = r / per_b; int rem = r - b * per_b;
    int idd = rem / nhc; int ihh = rem - idd * nhc;
    int od = 2 * idd + pd, oh = 2 * ihh + ph;

    const float* xb = x + (size_t)b * XB;
    float* op = out + ((size_t)(b * 31 + od) * 63 + oh) * 63;

    int id0, id1 = 0, ih0, ih1 = 0;
    if (pd) { id0 = (od + 1) >> 1; id1 = (od - 1) >> 1; } else id0 = od >> 1;
    if (ph) { ih0 = (oh + 1) >> 1; ih1 = (oh - 1) >> 1; } else ih0 = oh >> 1;

    if (cls == 0)      run_oct<1, 1>(xb, sw, op, id0, id1, ih0, ih1, c, bv);
    else if (cls == 1) run_oct<1, 2>(xb, sw, op, id0, id1, ih0, ih1, c, bv);
    else               run_oct<2, 1>(xb, sw, op, id0, id1, ih0, ih1, c, bv);
}

extern "C" void kernel_launch(void* const* d_in, const int* in_sizes, int n_in,
                              void* d_out, int out_size)
{
    const float* x    = (const float*)d_in[0];
    const float* w    = (const float*)d_in[1];
    const float* bias = (const float*)d_in[2];
    float* out        = (float*)d_out;

    convT_lse_v13<<<4836, 128>>>(x, w, bias, out);
}

// round 14
// speedup vs baseline: 1.2112x; 1.0091x over previous
#include <cuda_runtime.h>

// x: (32,3,16,32,32) fp32; weight: (3,16,3,3,3); bias scalar; out: (32,1,31,63,63)
// ConvTranspose3d s=2 p=1 k=3: per dim even o -> tap k=1 (i=o/2);
// odd o -> k=0 (i=(o+1)/2), k=2 (i=(o-1)/2). All in-range (od<=30, oh/ow<=62).

#define DIN 16
#define HIN 32
#define WIN 32
#define XCH (DIN*HIN*WIN)   // 16384
#define XB  (3*XCH)         // 49152
#define WSH (16*3*3*12)     // sw[oc][kd][kh][slot], slot=ic*3+kw (9 used, pad 12)
#define LOG2E 1.4426950408889634f
#define LN2   0.6931471805599453f

__device__ __forceinline__ float ex2f(float x) {
    float r; asm("ex2.approx.ftz.f32 %0, %1;" : "=f"(r) : "f"(x)); return r;
}
__device__ __forceinline__ float lg2f(float x) {
    float r; asm("lg2.approx.ftz.f32 %0, %1;" : "=f"(r) : "f"(x)); return r;
}

// Weights pre-scaled by log2(e): conv accumulators live in log2 domain; exp = one EX2.
__device__ __forceinline__ void load_weights(const float* __restrict__ w, float* sw) {
    // src w[ic*432 + oc*27 + kd*9 + kh*3 + kw]
    for (int i = threadIdx.x; i < 1296; i += 128) {
        int ic = i / 432;  int r = i - ic * 432;
        int oc = r / 27;   int tap = r - oc * 27;
        int kd = tap / 9;  int t2 = tap - kd * 9;
        int kh = t2 / 3;   int kw = t2 - kh * 3;
        sw[((oc * 3 + kd) * 3 + kh) * 12 + ic * 3 + kw] = w[i] * LOG2E;
    }
}

// s = sum_oc e^conv. Pure MUFU epilogue (LG2/EX2/RCP):
__device__ __forceinline__ float finish(float s, float bv) {
    float l2 = lg2f(s);
    float e  = ex2f(-l2 - 3.0f * LOG2E);
    float l  = l2 * LN2;
    float h  = __fdividef(l, fmaf(e, 6.f, 6.f));
    return fminf(fmaxf(h - bv, -1.f), 1.f);
}

// ---------------- width-8 path (classes with ND*NH <= 2) ----------------
// Lane c = lane&7 handles ow = 8c..8c+7 (c==7: ow 63 masked). 4 rows per warp.
// Edge value x[iw0+4] = next lane's t.x via shfl (halves LDG count; garbage for
// c==7 only feeds the masked ow=63 output).
template<int ND, int NH>
__device__ __forceinline__ void run_oct(
    const float* __restrict__ xb, const float* __restrict__ sw,
    float* __restrict__ op, int id0, int id1, int ih0, int ih1, int c, float bv)
{
    float xv[ND][NH][3][5];
    int iw0 = 4 * c;
    #pragma unroll
    for (int a = 0; a < ND; a++) {
        int idv = (a == 0) ? id0 : id1;
        #pragma unroll
        for (int h = 0; h < NH; h++) {
            int ihv = (h == 0) ? ih0 : ih1;
            const float* p = xb + idv * (HIN * WIN) + ihv * WIN;
            #pragma unroll
            for (int ic = 0; ic < 3; ic++) {
                float4 t = __ldg((const float4*)(p + ic * XCH + iw0));  // 16B aligned
                xv[a][h][ic][0] = t.x; xv[a][h][ic][1] = t.y;
                xv[a][h][ic][2] = t.z; xv[a][h][ic][3] = t.w;
                // x[iw0+4] == lane (c+1)'s t.x; c==7 gets other-row garbage (masked)
                xv[a][h][ic][4] = __shfl_down_sync(0xffffffffu, t.x, 1);
            }
        }
    }

    float s[8];
    #pragma unroll
    for (int k = 0; k < 8; k++) s[k] = 0.f;

    #pragma unroll
    for (int oc = 0; oc < 16; oc++) {
        float v[8];
        #pragma unroll
        for (int k = 0; k < 8; k++) v[k] = 0.f;
        #pragma unroll
        for (int a = 0; a < ND; a++) {
            const int KD = (ND == 1) ? 1 : a * 2;
            #pragma unroll
            for (int h = 0; h < NH; h++) {
                const int KH = (NH == 1) ? 1 : h * 2;
                const float* g = sw + ((oc * 3 + KD) * 3 + KH) * 12;
                float4 A = *(const float4*)g;
                float4 B = *(const float4*)(g + 4);
                float  C = g[8];
                #pragma unroll
                for (int t = 0; t < 4; t++) {
                    float x0t = xv[a][h][0][t], x1t = xv[a][h][1][t], x2t = xv[a][h][2][t];
                    float x0n = xv[a][h][0][t+1], x1n = xv[a][h][1][t+1], x2n = xv[a][h][2][t+1];
                    v[2*t]   = fmaf(A.y, x0t, v[2*t]);
                    v[2*t]   = fmaf(B.x, x1t, v[2*t]);
                    v[2*t]   = fmaf(B.w, x2t, v[2*t]);
                    v[2*t+1] = fmaf(A.x, x0n, v[2*t+1]);
                    v[2*t+1] = fmaf(A.w, x1n, v[2*t+1]);
                    v[2*t+1] = fmaf(B.z, x2n, v[2*t+1]);
                    v[2*t+1] = fmaf(A.z, x0t, v[2*t+1]);
                    v[2*t+1] = fmaf(B.y, x1t, v[2*t+1]);
                    v[2*t+1] = fmaf(C,   x2t, v[2*t+1]);
                }
            }
        }
        #pragma unroll
        for (int k = 0; k < 8; k++) s[k] += ex2f(v[k]);   // v in log2 domain
    }

    int wb = 8 * c;
    #pragma unroll
    for (int k = 0; k < 7; k++) op[wb + k] = finish(s[k], bv);
    if (c < 7) op[wb + 7] = finish(s[7], bv);
}

// ---------------- width-4 path (class 3: odd od, odd oh) ----------------
// Edge value x[iw0+2] = next lane's t.x via shfl (c==15 garbage -> masked ow=63).
__device__ __forceinline__ void run_quad22(
    const float* __restrict__ xb, const float* __restrict__ sw,
    float* __restrict__ op, int id0, int id1, int ih0, int ih1, int c, float bv)
{
    float xv[2][2][3][3];
    int iw0 = 2 * c;
    #pragma unroll
    for (int a = 0; a < 2; a++) {
        int idv = (a == 0) ? id0 : id1;
        #pragma unroll
        for (int h = 0; h < 2; h++) {
            int ihv = (h == 0) ? ih0 : ih1;
            const float* p = xb + idv * (HIN * WIN) + ihv * WIN;
            #pragma unroll
            for (int ic = 0; ic < 3; ic++) {
                float2 t = __ldg((const float2*)(p + ic * XCH + iw0));
                xv[a][h][ic][0] = t.x;
                xv[a][h][ic][1] = t.y;
                xv[a][h][ic][2] = __shfl_down_sync(0xffffffffu, t.x, 1);
            }
        }
    }

    float s0 = 0.f, s1 = 0.f, s2 = 0.f, s3 = 0.f;
    #pragma unroll
    for (int oc = 0; oc < 16; oc++) {
        float v0 = 0.f, v1 = 0.f, v2 = 0.f, v3 = 0.f;
        #pragma unroll
        for (int a = 0; a < 2; a++) {
            const int KD = a * 2;
            #pragma unroll
            for (int h = 0; h < 2; h++) {
                const int KH = h * 2;
                const float* g = sw + ((oc * 3 + KD) * 3 + KH) * 12;
                float4 A = *(const float4*)g;
                float4 B = *(const float4*)(g + 4);
                float  C = g[8];
                float x00 = xv[a][h][0][0], x01 = xv[a][h][0][1], x02 = xv[a][h][0][2];
                float x10 = xv[a][h][1][0], x11 = xv[a][h][1][1], x12 = xv[a][h][1][2];
                float x20 = xv[a][h][2][0], x21 = xv[a][h][2][1], x22 = xv[a][h][2][2];
                v0 = fmaf(A.y, x00, v0); v0 = fmaf(B.x, x10, v0); v0 = fmaf(B.w, x20, v0);
                v2 = fmaf(A.y, x01, v2); v2 = fmaf(B.x, x11, v2); v2 = fmaf(B.w, x21, v2);
                v1 = fmaf(A.x, x01, v1); v1 = fmaf(A.w, x11, v1); v1 = fmaf(B.z, x21, v1);
                v1 = fmaf(A.z, x00, v1); v1 = fmaf(B.y, x10, v1); v1 = fmaf(C,   x20, v1);
                v3 = fmaf(A.x, x02, v3); v3 = fmaf(A.w, x12, v3); v3 = fmaf(B.z, x22, v3);
                v3 = fmaf(A.z, x01, v3); v3 = fmaf(B.y, x11, v3); v3 = fmaf(C,   x21, v3);
            }
        }
        s0 += ex2f(v0); s1 += ex2f(v1); s2 += ex2f(v2); s3 += ex2f(v3);
    }

    int wb = 4 * c;
    op[wb]     = finish(s0, bv);
    op[wb + 1] = finish(s1, bv);
    op[wb + 2] = finish(s2, bv);
    if (wb + 3 < 63) op[wb + 3] = finish(s3, bv);
}

// Merged kernel, 128-thread blocks, min 8 blocks/SM (forces regs <= 64).
//   [0,1860):     cls3, width-4,  8 rows/block (14880 rows)
//   [1860,2884):  cls0, width-8, 16 rows/block (16384 rows)
//   [2884,3876):  cls1, width-8 (15872 rows)
//   [3876,4836):  cls2, width-8 (15360 rows)
__global__ __launch_bounds__(128, 8)
void convT_lse_v14(const float* __restrict__ x, const float* __restrict__ w,
                   const float* __restrict__ bias, float* __restrict__ out)
{
    __shared__ __align__(16) float sw[WSH];
    load_weights(w, sw);
    __syncthreads();

    int warp = threadIdx.x >> 5, lane = threadIdx.x & 31;
    float bv = __ldg(bias);
    int blk = blockIdx.x;

    if (blk < 1860) {
        int half = lane >> 4, c = lane & 15;
        int r = (blk * 4 + warp) * 2 + half;
        const int per_b = 15 * 31;
        int b = r / per_b; int rem = r - b * per_b;
        int idd = rem / 31; int ihh = rem - idd * 31;
        int od = 2 * idd + 1, oh = 2 * ihh + 1;
        const float* xb = x + (size_t)b * XB;
        float* op = out + ((size_t)(b * 31 + od) * 63 + oh) * 63;
        int id0 = (od + 1) >> 1, id1 = (od - 1) >> 1;
        int ih0 = (oh + 1) >> 1, ih1 = (oh - 1) >> 1;
        run_quad22(xb, sw, op, id0, id1, ih0, ih1, c, bv);
        return;
    }

    int rloc = lane >> 3, c = lane & 7;
    int cls, rb;
    if (blk < 2884)      { cls = 0; rb = (blk - 1860) * 16; }
    else if (blk < 3876) { cls = 1; rb = (blk - 2884) * 16; }
    else                 { cls = 2; rb = (blk - 3876) * 16; }
    int r = rb + warp * 4 + rloc;

    int pd = (cls == 2), ph = (cls == 1);
    int nhc = ph ? 31 : 32;
    int per_b = (pd ? 15 : 16) * nhc;
    int b = r / per_b; int rem = r - b * per_b;
    int idd = rem / nhc; int ihh = rem - idd * nhc;
    int od = 2 * idd + pd, oh = 2 * ihh + ph;

    const float* xb = x + (size_t)b * XB;
    float* op = out + ((size_t)(b * 31 + od) * 63 + oh) * 63;

    int id0, id1 = 0, ih0, ih1 = 0;
    if (pd) { id0 = (od + 1) >> 1; id1 = (od - 1) >> 1; } else id0 = od >> 1;
    if (ph) { ih0 = (oh + 1) >> 1; ih1 = (oh - 1) >> 1; } else ih0 = oh >> 1;

    if (cls == 0)      run_oct<1, 1>(xb, sw, op, id0, id1, ih0, ih1, c, bv);
    else if (cls == 1) run_oct<1, 2>(xb, sw, op, id0, id1, ih0, ih1, c, bv);
    else               run_oct<2, 1>(xb, sw, op, id0, id1, ih0, ih1, c, bv);
}

extern "C" void kernel_launch(void* const* d_in, const int* in_sizes, int n_in,
                              void* d_out, int out_size)
{
    const float* x    = (const float*)d_in[0];
    const float* w    = (const float*)d_in[1];
    const float* bias = (const float*)d_in[2];
    float* out        = (float*)d_out;

    convT_lse_v14<<<4836, 128>>>(x, w, bias, out);
}